// round 3
// baseline (speedup 1.0000x reference)
#include <cuda_runtime.h>
#include <cuda_fp16.h>
#include <cstdint>
#include <cstddef>

// ---------------------------------------------------------------------------
// AWQ 4-bit linear:  out[M,N] = x[M,K] @ W[N,K]^T + bias[N]
//   M = 8192 (B*S), N = 11008 (O), K = 4096 (I)
// Build target is plain sm_103 (tcgen05 rejected by ptxas) -> use mma.sync
// (HMMA) + ldmatrix + cp.async multistage pipeline.
//   Stage 1: x fp32 -> fp16 scratch
//   Stage 2: dequant nibble-packed W -> fp16 scratch
//   Stage 3: GEMM BM=128 x BN=128 x BK=64, 4-stage cp.async, 8 warps,
//            warp tile 64x32 via mma.m16n8k16, fp32 accum, bias epilogue
// ---------------------------------------------------------------------------

static constexpr int Mdim = 8192;
static constexpr int Ndim = 11008;
static constexpr int Kdim = 4096;
static constexpr int NGRP = 64;

static constexpr int BM = 128;
static constexpr int BN = 128;
static constexpr int BK = 64;            // fp16 per k-iter = 128 bytes/row
static constexpr int NK = Kdim / BK;     // 64
static constexpr int NS = 4;             // pipeline stages

static constexpr int A_BYTES = BM * 128;             // 16 KB
static constexpr int B_BYTES = BN * 128;             // 16 KB
static constexpr int STAGE   = A_BYTES + B_BYTES;    // 32 KB
static constexpr int SMEM_TOTAL = NS * STAGE;        // 128 KB

// Scratch (allocation-free rule: __device__ globals)
__device__ static __align__(16) __half  g_xh[(size_t)Mdim * Kdim];        // 64 MB
__device__ static __align__(16) __half2 g_wh[(size_t)Ndim * (Kdim / 2)];  // 90 MB

// ---------------------------------------------------------------------------
__device__ __forceinline__ uint32_t smem_u32(const void* p) {
    return (uint32_t)__cvta_generic_to_shared(p);
}
__device__ __forceinline__ uint32_t sw128(uint32_t off) {   // SW128 XOR swizzle
    return off ^ ((off >> 3) & 0x70);
}
__device__ __forceinline__ void ldsm_x4(uint32_t* r, uint32_t addr) {
    asm volatile("ldmatrix.sync.aligned.m8n8.x4.shared.b16 {%0,%1,%2,%3}, [%4];\n"
                 : "=r"(r[0]), "=r"(r[1]), "=r"(r[2]), "=r"(r[3]) : "r"(addr));
}
__device__ __forceinline__ void mma16816(float* d, const uint32_t* a,
                                         uint32_t b0, uint32_t b1) {
    asm volatile(
        "mma.sync.aligned.m16n8k16.row.col.f32.f16.f16.f32 "
        "{%0,%1,%2,%3}, {%4,%5,%6,%7}, {%8,%9}, {%0,%1,%2,%3};\n"
        : "+f"(d[0]), "+f"(d[1]), "+f"(d[2]), "+f"(d[3])
        : "r"(a[0]), "r"(a[1]), "r"(a[2]), "r"(a[3]), "r"(b0), "r"(b1));
}

// ---------------------------------------------------------------------------
// Stage 1: x fp32 -> fp16
// ---------------------------------------------------------------------------
__global__ void k_convert_x(const float4* __restrict__ x) {
    int i = blockIdx.x * blockDim.x + threadIdx.x;
    float4 v = x[i];
    __half2 a = __floats2half2_rn(v.x, v.y);
    __half2 b = __floats2half2_rn(v.z, v.w);
    uint2 r;
    r.x = *reinterpret_cast<const unsigned*>(&a);
    r.y = *reinterpret_cast<const unsigned*>(&b);
    reinterpret_cast<uint2*>(g_xh)[i] = r;
}

// ---------------------------------------------------------------------------
// Stage 2: dequant W[o,2j]=(s*lo+z)*cs[2j], W[o,2j+1]=(s*hi+z)*cs[2j+1]
// ---------------------------------------------------------------------------
__global__ void k_dequant(const int* __restrict__ wq,
                          const float* __restrict__ scales,
                          const float* __restrict__ zeros,
                          const float2* __restrict__ cs2) {
    int i = blockIdx.x * blockDim.x + threadIdx.x;   // [0, N * K/2)
    int o = i >> 11;            // / (K/2 = 2048)
    int j = i & 2047;
    int q = wq[i];
    int g = j >> 5;             // 32 packed per group of 64 cols
    float s = scales[o * NGRP + g];
    float z = zeros[o * NGRP + g];
    float2 c = __ldg(&cs2[j]);
    float lo = fmaf(s, (float)(q & 15), z) * c.x;
    float hi = fmaf(s, (float)((q >> 4) & 15), z) * c.y;
    g_wh[i] = __floats2half2_rn(lo, hi);
}

// ---------------------------------------------------------------------------
// Stage 3: GEMM
// ---------------------------------------------------------------------------
__device__ __forceinline__ void load_stage(uint32_t sbase, int st,
                                           int m0, int n0, int kk, int tid) {
    uint32_t sA = sbase + st * STAGE;
    uint32_t sB = sA + A_BYTES;
    int koff = kk * BK;
    const __half* A  = g_xh;
    const __half* Bw = reinterpret_cast<const __half*>(g_wh);
#pragma unroll
    for (int c = 0; c < 4; c++) {
        int idx = tid + c * 256;            // 1024 16B chunks per tile
        int row = idx >> 3, ch = idx & 7;
        uint32_t off = (uint32_t)(row * 128 + ch * 16);
        uint32_t so  = sw128(off);
        const __half* a_src = A  + (size_t)(m0 + row) * Kdim + koff + ch * 8;
        const __half* b_src = Bw + (size_t)(n0 + row) * Kdim + koff + ch * 8;
        asm volatile("cp.async.cg.shared.global [%0], [%1], 16;\n"
                     :: "r"(sA + so), "l"(a_src));
        asm volatile("cp.async.cg.shared.global [%0], [%1], 16;\n"
                     :: "r"(sB + so), "l"(b_src));
    }
}

__global__ __launch_bounds__(256, 1)
void k_gemm(const float* __restrict__ bias, float* __restrict__ out) {
    extern __shared__ __align__(1024) char smem[];
    uint32_t sbase = smem_u32(smem);
    int tid = threadIdx.x;
    int lane = tid & 31;
    int w = tid >> 5;
    int m0 = blockIdx.y * BM;
    int n0 = blockIdx.x * BN;
    int wm = (w & 1) * 64;        // warp m-offset in CTA tile
    int wn = (w >> 1) * 32;       // warp n-offset

    float acc[4][4][4];
#pragma unroll
    for (int a = 0; a < 4; a++)
#pragma unroll
        for (int b = 0; b < 4; b++)
#pragma unroll
            for (int c = 0; c < 4; c++) acc[a][b][c] = 0.f;

    // Prologue: NS-1 stages in flight
#pragma unroll
    for (int s = 0; s < NS - 1; s++) {
        load_stage(sbase, s, m0, n0, s, tid);
        asm volatile("cp.async.commit_group;" ::: "memory");
    }

    // Per-thread ldmatrix offsets (within tile, pre-swizzled row part)
    int lrow = lane & 15;
    int lcol = (lane >> 4) * 16;   // byte offset of 8-col half

    for (int j = 0; j < NK; j++) {
        asm volatile("cp.async.wait_group %0;" :: "n"(NS - 2) : "memory");
        __syncthreads();
        int kn = j + NS - 1;
        if (kn < NK) load_stage(sbase, kn & (NS - 1), m0, n0, kn, tid);
        asm volatile("cp.async.commit_group;" ::: "memory");

        uint32_t sA = sbase + (j & (NS - 1)) * STAGE;
        uint32_t sB = sA + A_BYTES;
#pragma unroll
        for (int ks = 0; ks < 4; ks++) {        // 4 x k16 per BK=64
            uint32_t af[4][4], bf[2][4];
#pragma unroll
            for (int mi = 0; mi < 4; mi++) {
                uint32_t off = (uint32_t)((wm + mi * 16 + lrow) * 128 + ks * 32 + lcol);
                ldsm_x4(af[mi], sA + sw128(off));
            }
#pragma unroll
            for (int ni = 0; ni < 2; ni++) {
                uint32_t off = (uint32_t)((wn + ni * 16 + lrow) * 128 + ks * 32 + lcol);
                ldsm_x4(bf[ni], sB + sw128(off));
            }
#pragma unroll
            for (int mi = 0; mi < 4; mi++)
#pragma unroll
                for (int nj = 0; nj < 4; nj++)
                    mma16816(acc[mi][nj], af[mi],
                             bf[nj >> 1][nj & 1], bf[nj >> 1][(nj & 1) + 2]);
        }
    }

    // Epilogue: bias + store (each thread: float2 per (mi,nj) per row-half)
#pragma unroll
    for (int nj = 0; nj < 4; nj++) {
        int n = n0 + wn + nj * 8 + (lane & 3) * 2;
        float2 bv = *reinterpret_cast<const float2*>(bias + n);
#pragma unroll
        for (int mi = 0; mi < 4; mi++) {
            int m = m0 + wm + mi * 16 + (lane >> 2);
            float2 v0 = make_float2(acc[mi][nj][0] + bv.x, acc[mi][nj][1] + bv.y);
            float2 v1 = make_float2(acc[mi][nj][2] + bv.x, acc[mi][nj][3] + bv.y);
            *reinterpret_cast<float2*>(out + (size_t)m * Ndim + n) = v0;
            *reinterpret_cast<float2*>(out + (size_t)(m + 8) * Ndim + n) = v1;
        }
    }
}

// ---------------------------------------------------------------------------
extern "C" void kernel_launch(void* const* d_in, const int* in_sizes, int n_in,
                              void* d_out, int out_size) {
    const float* x         = (const float*)d_in[0];
    const int*   wq        = (const int*)d_in[1];
    const float* scales    = (const float*)d_in[2];
    const float* zeros     = (const float*)d_in[3];
    const float* col_scale = (const float*)d_in[4];
    const float* bias      = (const float*)d_in[5];
    float* out = (float*)d_out;
    (void)in_sizes; (void)n_in; (void)out_size;

    k_convert_x<<<(Mdim * Kdim / 4) / 256, 256>>>((const float4*)x);
    k_dequant<<<(Ndim * (Kdim / 2)) / 256, 256>>>(wq, scales, zeros,
                                                  (const float2*)col_scale);

    cudaFuncSetAttribute(k_gemm, cudaFuncAttributeMaxDynamicSharedMemorySize,
                         SMEM_TOTAL);
    dim3 grid(Ndim / BN, Mdim / BM);   // (86, 64)
    k_gemm<<<grid, 256, SMEM_TOTAL>>>(bias, out);
}

// round 8
// speedup vs baseline: 1.0712x; 1.0712x over previous
#include <cuda_runtime.h>
#include <cuda_fp16.h>
#include <cstdint>
#include <cstddef>

// ---------------------------------------------------------------------------
// AWQ 4-bit linear:  out[M,N] = x[M,K] @ W[N,K]^T + bias[N]
//   M = 8192, N = 11008, K = 4096
// mma.sync (HMMA) + ldmatrix + cp.async pipeline (tcgen05 rejected by the
// plain-sm_103 device pass of this build).
//   Stage 1: x fp32 -> fp16 scratch
//   Stage 2: dequant nibble-packed W -> fp16 scratch
//   Stage 3: GEMM BM=128 x BN=256 x BK=64, 4-stage cp.async, 8 warps,
//            warp tile 64x64 via mma.m16n8k16, fp32 accum, bias epilogue
// ---------------------------------------------------------------------------

static constexpr int Mdim = 8192;
static constexpr int Ndim = 11008;
static constexpr int Kdim = 4096;
static constexpr int NGRP = 64;

static constexpr int BM = 128;
static constexpr int BN = 256;
static constexpr int BK = 64;            // fp16 per k-iter = 128 bytes/row
static constexpr int NK = Kdim / BK;     // 64
static constexpr int NS = 4;             // pipeline stages

static constexpr int A_BYTES = BM * 128;             // 16 KB
static constexpr int B_BYTES = BN * 128;             // 32 KB
static constexpr int STAGE   = A_BYTES + B_BYTES;    // 48 KB
static constexpr int SMEM_TOTAL = NS * STAGE;        // 192 KB

// Scratch (allocation-free rule: __device__ globals)
__device__ static __align__(16) __half  g_xh[(size_t)Mdim * Kdim];        // 64 MB
__device__ static __align__(16) __half2 g_wh[(size_t)Ndim * (Kdim / 2)];  // 90 MB

// ---------------------------------------------------------------------------
__device__ __forceinline__ uint32_t smem_u32(const void* p) {
    return (uint32_t)__cvta_generic_to_shared(p);
}
__device__ __forceinline__ uint32_t sw128(uint32_t off) {   // SW128 XOR swizzle
    return off ^ ((off >> 3) & 0x70);
}
__device__ __forceinline__ void ldsm_x4(uint32_t* r, uint32_t addr) {
    asm volatile("ldmatrix.sync.aligned.m8n8.x4.shared.b16 {%0,%1,%2,%3}, [%4];\n"
                 : "=r"(r[0]), "=r"(r[1]), "=r"(r[2]), "=r"(r[3]) : "r"(addr));
}
__device__ __forceinline__ void mma16816(float* d, const uint32_t* a,
                                         uint32_t b0, uint32_t b1) {
    asm volatile(
        "mma.sync.aligned.m16n8k16.row.col.f32.f16.f16.f32 "
        "{%0,%1,%2,%3}, {%4,%5,%6,%7}, {%8,%9}, {%0,%1,%2,%3};\n"
        : "+f"(d[0]), "+f"(d[1]), "+f"(d[2]), "+f"(d[3])
        : "r"(a[0]), "r"(a[1]), "r"(a[2]), "r"(a[3]), "r"(b0), "r"(b1));
}

// ---------------------------------------------------------------------------
// Stage 1: x fp32 -> fp16
// ---------------------------------------------------------------------------
__global__ void k_convert_x(const float4* __restrict__ x) {
    int i = blockIdx.x * blockDim.x + threadIdx.x;
    float4 v = x[i];
    __half2 a = __floats2half2_rn(v.x, v.y);
    __half2 b = __floats2half2_rn(v.z, v.w);
    uint2 r;
    r.x = *reinterpret_cast<const unsigned*>(&a);
    r.y = *reinterpret_cast<const unsigned*>(&b);
    reinterpret_cast<uint2*>(g_xh)[i] = r;
}

// ---------------------------------------------------------------------------
// Stage 2: dequant W[o,2j]=(s*lo+z)*cs[2j], W[o,2j+1]=(s*hi+z)*cs[2j+1]
// ---------------------------------------------------------------------------
__global__ void k_dequant(const int* __restrict__ wq,
                          const float* __restrict__ scales,
                          const float* __restrict__ zeros,
                          const float2* __restrict__ cs2) {
    int i = blockIdx.x * blockDim.x + threadIdx.x;   // [0, N * K/2)
    int o = i >> 11;            // / (K/2 = 2048)
    int j = i & 2047;
    int q = wq[i];
    int g = j >> 5;             // 32 packed per group of 64 cols
    float s = scales[o * NGRP + g];
    float z = zeros[o * NGRP + g];
    float2 c = __ldg(&cs2[j]);
    float lo = fmaf(s, (float)(q & 15), z) * c.x;
    float hi = fmaf(s, (float)((q >> 4) & 15), z) * c.y;
    g_wh[i] = __floats2half2_rn(lo, hi);
}

// ---------------------------------------------------------------------------
// Stage 3: GEMM
// ---------------------------------------------------------------------------
__device__ __forceinline__ void load_stage(uint32_t sbase, int st,
                                           int m0, int n0, int kk, int tid) {
    uint32_t sA = sbase + st * STAGE;
    uint32_t sB = sA + A_BYTES;
    int koff = kk * BK;
    const __half* A  = g_xh;
    const __half* Bw = reinterpret_cast<const __half*>(g_wh);
    // A: 128 rows x 128B = 1024 16B chunks; 4 per thread
#pragma unroll
    for (int c = 0; c < 4; c++) {
        int idx = tid + c * 256;
        int row = idx >> 3, ch = idx & 7;
        uint32_t off = (uint32_t)(row * 128 + ch * 16);
        const __half* src = A + (size_t)(m0 + row) * Kdim + koff + ch * 8;
        asm volatile("cp.async.cg.shared.global [%0], [%1], 16;\n"
                     :: "r"(sA + sw128(off)), "l"(src));
    }
    // B: 256 rows x 128B = 2048 chunks; 8 per thread
#pragma unroll
    for (int c = 0; c < 8; c++) {
        int idx = tid + c * 256;
        int row = idx >> 3, ch = idx & 7;
        uint32_t off = (uint32_t)(row * 128 + ch * 16);
        const __half* src = Bw + (size_t)(n0 + row) * Kdim + koff + ch * 8;
        asm volatile("cp.async.cg.shared.global [%0], [%1], 16;\n"
                     :: "r"(sB + sw128(off)), "l"(src));
    }
}

__global__ __launch_bounds__(256, 1)
void k_gemm(const float* __restrict__ bias, float* __restrict__ out) {
    extern __shared__ __align__(1024) char smem[];
    uint32_t sbase = smem_u32(smem);
    int tid = threadIdx.x;
    int lane = tid & 31;
    int w = tid >> 5;
    int m0 = blockIdx.y * BM;
    int n0 = blockIdx.x * BN;
    int wm = (w & 1) * 64;        // 2 warps along M
    int wn = (w >> 1) * 64;       // 4 warps along N

    float acc[4][8][4];
#pragma unroll
    for (int a = 0; a < 4; a++)
#pragma unroll
        for (int b = 0; b < 8; b++)
#pragma unroll
            for (int c = 0; c < 4; c++) acc[a][b][c] = 0.f;

#pragma unroll
    for (int s = 0; s < NS - 1; s++) {
        load_stage(sbase, s, m0, n0, s, tid);
        asm volatile("cp.async.commit_group;" ::: "memory");
    }

    int lrow = lane & 15;
    int lcol = (lane >> 4) * 16;

    for (int j = 0; j < NK; j++) {
        asm volatile("cp.async.wait_group %0;" :: "n"(NS - 2) : "memory");
        __syncthreads();
        int kn = j + NS - 1;
        if (kn < NK) load_stage(sbase, kn & (NS - 1), m0, n0, kn, tid);
        asm volatile("cp.async.commit_group;" ::: "memory");

        uint32_t sA = sbase + (j & (NS - 1)) * STAGE;
        uint32_t sB = sA + A_BYTES;
#pragma unroll
        for (int ks = 0; ks < 4; ks++) {        // 4 x k16 per BK=64
            uint32_t af[4][4], bf[4][4];
#pragma unroll
            for (int mi = 0; mi < 4; mi++) {
                uint32_t off = (uint32_t)((wm + mi * 16 + lrow) * 128 + ks * 32 + lcol);
                ldsm_x4(af[mi], sA + sw128(off));
            }
#pragma unroll
            for (int ni = 0; ni < 4; ni++) {
                uint32_t off = (uint32_t)((wn + ni * 16 + lrow) * 128 + ks * 32 + lcol);
                ldsm_x4(bf[ni], sB + sw128(off));
            }
#pragma unroll
            for (int mi = 0; mi < 4; mi++)
#pragma unroll
                for (int nj = 0; nj < 8; nj++)
                    mma16816(acc[mi][nj], af[mi],
                             bf[nj >> 1][nj & 1], bf[nj >> 1][(nj & 1) + 2]);
        }
    }

    // Epilogue: bias + store
#pragma unroll
    for (int nj = 0; nj < 8; nj++) {
        int n = n0 + wn + nj * 8 + (lane & 3) * 2;
        float2 bv = *reinterpret_cast<const float2*>(bias + n);
#pragma unroll
        for (int mi = 0; mi < 4; mi++) {
            int m = m0 + wm + mi * 16 + (lane >> 2);
            float2 v0 = make_float2(acc[mi][nj][0] + bv.x, acc[mi][nj][1] + bv.y);
            float2 v1 = make_float2(acc[mi][nj][2] + bv.x, acc[mi][nj][3] + bv.y);
            *reinterpret_cast<float2*>(out + (size_t)m * Ndim + n) = v0;
            *reinterpret_cast<float2*>(out + (size_t)(m + 8) * Ndim + n) = v1;
        }
    }
}

// ---------------------------------------------------------------------------
extern "C" void kernel_launch(void* const* d_in, const int* in_sizes, int n_in,
                              void* d_out, int out_size) {
    const float* x         = (const float*)d_in[0];
    const int*   wq        = (const int*)d_in[1];
    const float* scales    = (const float*)d_in[2];
    const float* zeros     = (const float*)d_in[3];
    const float* col_scale = (const float*)d_in[4];
    const float* bias      = (const float*)d_in[5];
    float* out = (float*)d_out;
    (void)in_sizes; (void)n_in; (void)out_size;

    k_convert_x<<<(Mdim * Kdim / 4) / 256, 256>>>((const float4*)x);
    k_dequant<<<(Ndim * (Kdim / 2)) / 256, 256>>>(wq, scales, zeros,
                                                  (const float2*)col_scale);

    cudaFuncSetAttribute(k_gemm, cudaFuncAttributeMaxDynamicSharedMemorySize,
                         SMEM_TOTAL);
    dim3 grid(Ndim / BN, Mdim / BM);   // (43, 64)
    k_gemm<<<grid, 256, SMEM_TOTAL>>>(bias, out);
}

// round 11
// speedup vs baseline: 1.1966x; 1.1171x over previous
#include <cuda_runtime.h>
#include <cuda_fp16.h>
#include <cstdint>
#include <cstddef>

// ---------------------------------------------------------------------------
// AWQ 4-bit linear:  out[M,N] = x[M,K] @ W[N,K]^T + bias[N]
//   M = 8192, N = 11008, K = 4096
// mma.sync (HMMA) + ldmatrix + cp.async pipeline (tcgen05 rejected by the
// plain-sm_103 device pass of this build).
//   Stage 1: x fp32 -> fp16 scratch
//   Stage 2: dequant nibble-packed W -> fp16 scratch
//   Stage 3: GEMM BM=128 x BN=128 x BK=64, 3-stage cp.async, 8 warps,
//            warp tile 64x32, TWO CTAs per SM (occupancy-driven), fp32 accum
// ---------------------------------------------------------------------------

static constexpr int Mdim = 8192;
static constexpr int Ndim = 11008;
static constexpr int Kdim = 4096;
static constexpr int NGRP = 64;

static constexpr int BM = 128;
static constexpr int BN = 128;
static constexpr int BK = 64;            // fp16 per k-iter = 128 bytes/row
static constexpr int NK = Kdim / BK;     // 64
static constexpr int NS = 3;             // pipeline stages (ring of 3)

static constexpr int A_BYTES = BM * 128;             // 16 KB
static constexpr int B_BYTES = BN * 128;             // 16 KB
static constexpr int STAGE   = A_BYTES + B_BYTES;    // 32 KB
static constexpr int SMEM_TOTAL = NS * STAGE;        // 96 KB -> 2 CTAs/SM

// Scratch (allocation-free rule: __device__ globals)
__device__ static __align__(16) __half  g_xh[(size_t)Mdim * Kdim];        // 64 MB
__device__ static __align__(16) __half2 g_wh[(size_t)Ndim * (Kdim / 2)];  // 90 MB

// ---------------------------------------------------------------------------
__device__ __forceinline__ uint32_t smem_u32(const void* p) {
    return (uint32_t)__cvta_generic_to_shared(p);
}
__device__ __forceinline__ uint32_t sw128(uint32_t off) {   // SW128 XOR swizzle
    return off ^ ((off >> 3) & 0x70);
}
__device__ __forceinline__ void ldsm_x4(uint32_t* r, uint32_t addr) {
    asm volatile("ldmatrix.sync.aligned.m8n8.x4.shared.b16 {%0,%1,%2,%3}, [%4];\n"
                 : "=r"(r[0]), "=r"(r[1]), "=r"(r[2]), "=r"(r[3]) : "r"(addr));
}
__device__ __forceinline__ void mma16816(float* d, const uint32_t* a,
                                         uint32_t b0, uint32_t b1) {
    asm volatile(
        "mma.sync.aligned.m16n8k16.row.col.f32.f16.f16.f32 "
        "{%0,%1,%2,%3}, {%4,%5,%6,%7}, {%8,%9}, {%0,%1,%2,%3};\n"
        : "+f"(d[0]), "+f"(d[1]), "+f"(d[2]), "+f"(d[3])
        : "r"(a[0]), "r"(a[1]), "r"(a[2]), "r"(a[3]), "r"(b0), "r"(b1));
}

// ---------------------------------------------------------------------------
// Stage 1: x fp32 -> fp16
// ---------------------------------------------------------------------------
__global__ void k_convert_x(const float4* __restrict__ x) {
    int i = blockIdx.x * blockDim.x + threadIdx.x;
    float4 v = x[i];
    __half2 a = __floats2half2_rn(v.x, v.y);
    __half2 b = __floats2half2_rn(v.z, v.w);
    uint2 r;
    r.x = *reinterpret_cast<const unsigned*>(&a);
    r.y = *reinterpret_cast<const unsigned*>(&b);
    reinterpret_cast<uint2*>(g_xh)[i] = r;
}

// ---------------------------------------------------------------------------
// Stage 2: dequant W[o,2j]=(s*lo+z)*cs[2j], W[o,2j+1]=(s*hi+z)*cs[2j+1]
// ---------------------------------------------------------------------------
__global__ void k_dequant(const int* __restrict__ wq,
                          const float* __restrict__ scales,
                          const float* __restrict__ zeros,
                          const float2* __restrict__ cs2) {
    int i = blockIdx.x * blockDim.x + threadIdx.x;   // [0, N * K/2)
    int o = i >> 11;            // / (K/2 = 2048)
    int j = i & 2047;
    int q = wq[i];
    int g = j >> 5;             // 32 packed per group of 64 cols
    float s = scales[o * NGRP + g];
    float z = zeros[o * NGRP + g];
    float2 c = __ldg(&cs2[j]);
    float lo = fmaf(s, (float)(q & 15), z) * c.x;
    float hi = fmaf(s, (float)((q >> 4) & 15), z) * c.y;
    g_wh[i] = __floats2half2_rn(lo, hi);
}

// ---------------------------------------------------------------------------
// Stage 3: GEMM
// ---------------------------------------------------------------------------
__device__ __forceinline__ void load_stage(uint32_t sbase, int st,
                                           int m0, int n0, int kk, int tid) {
    uint32_t sA = sbase + st * STAGE;
    uint32_t sB = sA + A_BYTES;
    int koff = kk * BK;
    const __half* A  = g_xh;
    const __half* Bw = reinterpret_cast<const __half*>(g_wh);
    // A and B: each 128 rows x 128B = 1024 16B chunks; 4 per thread each
#pragma unroll
    for (int c = 0; c < 4; c++) {
        int idx = tid + c * 256;
        int row = idx >> 3, ch = idx & 7;
        uint32_t off = (uint32_t)(row * 128 + ch * 16);
        uint32_t so  = sw128(off);
        const __half* a_src = A  + (size_t)(m0 + row) * Kdim + koff + ch * 8;
        const __half* b_src = Bw + (size_t)(n0 + row) * Kdim + koff + ch * 8;
        asm volatile("cp.async.cg.shared.global [%0], [%1], 16;\n"
                     :: "r"(sA + so), "l"(a_src));
        asm volatile("cp.async.cg.shared.global [%0], [%1], 16;\n"
                     :: "r"(sB + so), "l"(b_src));
    }
}

__global__ __launch_bounds__(256, 2)
void k_gemm(const float* __restrict__ bias, float* __restrict__ out) {
    extern __shared__ __align__(1024) char smem[];
    uint32_t sbase = smem_u32(smem);
    int tid = threadIdx.x;
    int lane = tid & 31;
    int w = tid >> 5;
    int m0 = blockIdx.y * BM;
    int n0 = blockIdx.x * BN;
    int wm = (w & 1) * 64;        // 2 warps along M
    int wn = (w >> 1) * 32;       // 4 warps along N

    float acc[4][4][4];
#pragma unroll
    for (int a = 0; a < 4; a++)
#pragma unroll
        for (int b = 0; b < 4; b++)
#pragma unroll
            for (int c = 0; c < 4; c++) acc[a][b][c] = 0.f;

    // Prologue: NS-1 = 2 stages in flight
#pragma unroll
    for (int s = 0; s < NS - 1; s++) {
        load_stage(sbase, s, m0, n0, s, tid);
        asm volatile("cp.async.commit_group;" ::: "memory");
    }

    int lrow = lane & 15;
    int lcol = (lane >> 4) * 16;

    int cs = 0;           // compute stage (ring of 3)
    int ls = NS - 1;      // load stage for k-iter j + NS-1

    for (int j = 0; j < NK; j++) {
        asm volatile("cp.async.wait_group %0;" :: "n"(NS - 2) : "memory");
        __syncthreads();
        int kn = j + NS - 1;
        if (kn < NK) load_stage(sbase, ls, m0, n0, kn, tid);
        asm volatile("cp.async.commit_group;" ::: "memory");

        uint32_t sA = sbase + cs * STAGE;
        uint32_t sB = sA + A_BYTES;
#pragma unroll
        for (int ks = 0; ks < 4; ks++) {        // 4 x k16 per BK=64
            uint32_t af[4][4], bf[2][4];
#pragma unroll
            for (int mi = 0; mi < 4; mi++) {
                uint32_t off = (uint32_t)((wm + mi * 16 + lrow) * 128 + ks * 32 + lcol);
                ldsm_x4(af[mi], sA + sw128(off));
            }
#pragma unroll
            for (int ni = 0; ni < 2; ni++) {
                uint32_t off = (uint32_t)((wn + ni * 16 + lrow) * 128 + ks * 32 + lcol);
                ldsm_x4(bf[ni], sB + sw128(off));
            }
#pragma unroll
            for (int mi = 0; mi < 4; mi++)
#pragma unroll
                for (int nj = 0; nj < 4; nj++)
                    mma16816(acc[mi][nj], af[mi],
                             bf[nj >> 1][nj & 1], bf[nj >> 1][(nj & 1) + 2]);
        }
        cs = (cs + 1 == NS) ? 0 : cs + 1;
        ls = (ls + 1 == NS) ? 0 : ls + 1;
    }

    // Epilogue: bias + store
#pragma unroll
    for (int nj = 0; nj < 4; nj++) {
        int n = n0 + wn + nj * 8 + (lane & 3) * 2;
        float2 bv = *reinterpret_cast<const float2*>(bias + n);
#pragma unroll
        for (int mi = 0; mi < 4; mi++) {
            int m = m0 + wm + mi * 16 + (lane >> 2);
            float2 v0 = make_float2(acc[mi][nj][0] + bv.x, acc[mi][nj][1] + bv.y);
            float2 v1 = make_float2(acc[mi][nj][2] + bv.x, acc[mi][nj][3] + bv.y);
            *reinterpret_cast<float2*>(out + (size_t)m * Ndim + n) = v0;
            *reinterpret_cast<float2*>(out + (size_t)(m + 8) * Ndim + n) = v1;
        }
    }
}

// ---------------------------------------------------------------------------
extern "C" void kernel_launch(void* const* d_in, const int* in_sizes, int n_in,
                              void* d_out, int out_size) {
    const float* x         = (const float*)d_in[0];
    const int*   wq        = (const int*)d_in[1];
    const float* scales    = (const float*)d_in[2];
    const float* zeros     = (const float*)d_in[3];
    const float* col_scale = (const float*)d_in[4];
    const float* bias      = (const float*)d_in[5];
    float* out = (float*)d_out;
    (void)in_sizes; (void)n_in; (void)out_size;

    k_convert_x<<<(Mdim * Kdim / 4) / 256, 256>>>((const float4*)x);
    k_dequant<<<(Ndim * (Kdim / 2)) / 256, 256>>>(wq, scales, zeros,
                                                  (const float2*)col_scale);

    cudaFuncSetAttribute(k_gemm, cudaFuncAttributeMaxDynamicSharedMemorySize,
                         SMEM_TOTAL);
    dim3 grid(Ndim / BN, Mdim / BM);   // (86, 64)
    k_gemm<<<grid, 256, SMEM_TOTAL>>>(bias, out);
}